// round 2
// baseline (speedup 1.0000x reference)
#include <cuda_runtime.h>

#define BB 4096
#define DD 64
#define HH8 8
#define CC 16384
#define CSPLIT 8
#define CKEYS (CC / CSPLIT)
#define TAU 0.3f

// ---- scratch offsets (floats) ----
constexpr int OFF_AT    = 0;
constexpr int OFF_APART = OFF_AT    + 4096;
constexpr int OFF_KN    = OFF_APART + 32768;
constexpr int OFF_Q     = OFF_KN    + 1048576;
constexpr int OFF_QN    = OFF_Q     + 262144;
constexpr int OFF_VMEM  = OFF_QN    + 262144;
constexpr int OFF_VC    = OFF_VMEM  + 262144;
constexpr int OFF_PVAL  = OFF_VC    + 262144;
constexpr int OFF_PIDX  = OFF_PVAL  + 131072;
constexpr int OFF_ZH    = OFF_PIDX  + 131072;
constexpr int OFF_X     = OFF_ZH    + 262144;
constexpr int OFF_GI    = OFF_X     + 524288;
constexpr int OFF_GH    = OFF_GI    + 1572864;
constexpr int OFF_H0B   = OFF_GH    + 1572864;
constexpr int OFF_H2A   = OFF_H0B   + 524288;
constexpr int OFF_H2B   = OFF_H2A   + 524288;
constexpr int OFF_HID   = OFF_H2B   + 524288;
constexpr int OFF_Z1    = OFF_HID   + 524288;
constexpr int OFF_Z2    = OFF_Z1    + 262144;
constexpr int OFF_CAT   = OFF_Z2    + 262144;
constexpr int OFF_ZE    = OFF_CAT   + 524288;
constexpr int OFF_CFP   = OFF_ZE    + 262144;
constexpr int OFF_ZERO  = OFF_CFP   + 256;
constexpr int SCR_TOTAL = OFF_ZERO  + 512;

__device__ float d_scr[SCR_TOTAL];

// ---- prep: Apart[h] = Wk_h^T @ (mem_h @ Wo^T) ----
__global__ void prepA_kernel(const float* __restrict__ mem,
                             const float* __restrict__ Wk,
                             const float* __restrict__ Wo,
                             float* __restrict__ Apart)
{
    int h = blockIdx.x;
    __shared__ float WoT[64 * 65];
    __shared__ float Mh[64 * 64];
    int t = threadIdx.x;
    #pragma unroll
    for (int p = 0; p < 16; p++) {
        int e = t + p * 256;
        int r = e >> 6, c = e & 63;
        WoT[c * 65 + r] = Wo[e];
    }
    __syncthreads();
    #pragma unroll
    for (int p = 0; p < 16; p++) {
        int e = t + p * 256;
        int dp = e >> 6, j = e & 63;
        const float* mrow = mem + h * 4096 + dp * 64;
        float s = 0.f;
        #pragma unroll
        for (int ee = 0; ee < 64; ee++) s += mrow[ee] * WoT[ee * 65 + j];
        Mh[dp * 64 + j] = s;
    }
    __syncthreads();
    #pragma unroll
    for (int p = 0; p < 16; p++) {
        int e = t + p * 256;
        int i = e >> 6, j = e & 63;
        float s = 0.f;
        #pragma unroll
        for (int dp = 0; dp < 64; dp++)
            s += Wk[(h * 64 + dp) * 64 + i] * Mh[dp * 64 + j];
        Apart[h * 4096 + e] = s;
    }
}

__global__ void reduceAT_kernel(const float* __restrict__ Apart,
                                float* __restrict__ AT)
{
    int e = blockIdx.x * 256 + threadIdx.x;
    int i = e >> 6, j = e & 63;
    float s = 0.f;
    #pragma unroll
    for (int h = 0; h < HH8; h++) s += Apart[h * 4096 + e];
    AT[j * 64 + i] = s * 0.125f;
}

// ---- elementwise ----
__global__ void mul_kernel(const float* __restrict__ a, const float* __restrict__ b,
                           float* __restrict__ o)
{
    int i = blockIdx.x * 256 + threadIdx.x;
    o[i] = a[i] * b[i];
}

__global__ void normalize_rows_kernel(const float* __restrict__ src,
                                      float* __restrict__ dst)
{
    int row  = blockIdx.x * 8 + (threadIdx.x >> 5);
    int lane = threadIdx.x & 31;
    float a = src[row * 64 + lane];
    float b = src[row * 64 + 32 + lane];
    float ss = a * a + b * b;
    #pragma unroll
    for (int off = 16; off > 0; off >>= 1)
        ss += __shfl_xor_sync(0xffffffffu, ss, off);
    float inv = 1.0f / fmaxf(sqrtf(ss), 1e-8f);
    dst[row * 64 + lane]      = a * inv;
    dst[row * 64 + 32 + lane] = b * inv;
}

__global__ void hinit_kernel(const float* __restrict__ h0, float* __restrict__ hb)
{
    int i = blockIdx.x * 256 + threadIdx.x;
    hb[i] = h0[i & 127];
}

__global__ void buildx_kernel(const float* __restrict__ zprev,
                              const float* __restrict__ aemb,
                              const int* __restrict__ actions, int t,
                              float* __restrict__ x)
{
    int i = blockIdx.x * 256 + threadIdx.x;
    int b = i >> 7, p = i & 127;
    if (p < 64) x[i] = zprev[b * 64 + p];
    else        x[i] = aemb[actions[b * 2 + t] * 64 + (p - 64)];
}

__global__ void cat_kernel(const float* __restrict__ z, const float* __restrict__ vc,
                           float* __restrict__ o)
{
    int i = blockIdx.x * 256 + threadIdx.x;
    int b = i >> 7, p = i & 127;
    o[i] = (p < 64) ? z[b * 64 + p] : vc[b * 64 + (p - 64)];
}

__global__ void gates_kernel(const float* __restrict__ gi, const float* __restrict__ gh,
                             const float* __restrict__ hprev, float* __restrict__ h2)
{
    int i = blockIdx.x * 256 + threadIdx.x;
    int b = i >> 7, j = i & 127;
    const float* gib = gi + b * 384;
    const float* ghb = gh + b * 384;
    float r = 1.0f / (1.0f + expf(-(gib[j] + ghb[j])));
    float u = 1.0f / (1.0f + expf(-(gib[128 + j] + ghb[128 + j])));
    float n = tanhf(gib[256 + j] + r * ghb[256 + j]);
    float h = hprev[i];
    h2[i] = (1.0f - u) * n + u * h;
}

__global__ void select_kernel(const float* __restrict__ z, const float* __restrict__ ze,
                              const float* __restrict__ gap, float* __restrict__ out)
{
    int i = blockIdx.x * 256 + threadIdx.x;
    int b = i >> 6;
    out[i] = (gap[b] > TAU) ? ze[i] : z[i];
}

// ---- tiled GEMM: C = act(A @ W^T + bias), M=4096, tiles 64x64, k-step 16 ----
__global__ __launch_bounds__(256) void gemm_kernel(
    const float* __restrict__ A, const float* __restrict__ W,
    const float* __restrict__ bias, float* __restrict__ Cm,
    int N, int K, int act)
{
    __shared__ float As[16 * 68];
    __shared__ float Ws[16 * 68];
    int tid = threadIdx.x;
    int tx = tid & 15, ty = tid >> 4;
    int m0 = blockIdx.x * 64, n0 = blockIdx.y * 64;
    float acc[16];
    #pragma unroll
    for (int q = 0; q < 16; q++) acc[q] = 0.f;
    int li = tid >> 2;
    int lj = (tid & 3) * 4;
    for (int kt = 0; kt < K; kt += 16) {
        float4 av = *(const float4*)(A + (size_t)(m0 + li) * K + kt + lj);
        float4 wv = *(const float4*)(W + (size_t)(n0 + li) * K + kt + lj);
        As[(lj + 0) * 68 + li] = av.x; As[(lj + 1) * 68 + li] = av.y;
        As[(lj + 2) * 68 + li] = av.z; As[(lj + 3) * 68 + li] = av.w;
        Ws[(lj + 0) * 68 + li] = wv.x; Ws[(lj + 1) * 68 + li] = wv.y;
        Ws[(lj + 2) * 68 + li] = wv.z; Ws[(lj + 3) * 68 + li] = wv.w;
        __syncthreads();
        #pragma unroll
        for (int k = 0; k < 16; k++) {
            float4 a = *(const float4*)(As + k * 68 + ty * 4);
            float4 b = *(const float4*)(Ws + k * 68 + tx * 4);
            acc[0]+=a.x*b.x; acc[1]+=a.x*b.y; acc[2]+=a.x*b.z; acc[3]+=a.x*b.w;
            acc[4]+=a.y*b.x; acc[5]+=a.y*b.y; acc[6]+=a.y*b.z; acc[7]+=a.y*b.w;
            acc[8]+=a.z*b.x; acc[9]+=a.z*b.y; acc[10]+=a.z*b.z; acc[11]+=a.z*b.w;
            acc[12]+=a.w*b.x; acc[13]+=a.w*b.y; acc[14]+=a.w*b.z; acc[15]+=a.w*b.w;
        }
        __syncthreads();
    }
    float4 bs = *(const float4*)(bias + n0 + tx * 4);
    float bcol[4] = {bs.x, bs.y, bs.z, bs.w};
    #pragma unroll
    for (int rr = 0; rr < 4; rr++) {
        int m = m0 + ty * 4 + rr;
        float4 o;
        float* op = (float*)&o;
        #pragma unroll
        for (int cc = 0; cc < 4; cc++) {
            float v = acc[rr * 4 + cc] + bcol[cc];
            if (act == 1) v = 0.5f * v * (1.0f + erff(v * 0.70710678118654752f));
            op[cc] = v;
        }
        *(float4*)(Cm + (size_t)m * N + n0 + tx * 4) = o;
    }
}

// ---- sims + per-split top-4 ----
#define BETTER(v,id,V,I) ((v) > (V) || ((v) == (V) && (id) < (I)))

__global__ __launch_bounds__(256) void sims_topk_kernel(
    const float* __restrict__ qn, const float* __restrict__ kn,
    float* __restrict__ pval, int* __restrict__ pidx)
{
    __shared__ float q_s[64 * 68];
    __shared__ float k_s[64 * 68];
    int tid = threadIdx.x;
    int tx = tid & 15, ty = tid >> 4;
    int row0 = blockIdx.x * 64;
    int c0 = blockIdx.y * CKEYS;

    #pragma unroll
    for (int p = 0; p < 4; p++) {
        int flat = p * 1024 + tid * 4;
        int i = flat >> 6, k = flat & 63;
        float4 v = *(const float4*)(qn + (size_t)(row0 + i) * 64 + k);
        q_s[(k + 0) * 68 + i] = v.x; q_s[(k + 1) * 68 + i] = v.y;
        q_s[(k + 2) * 68 + i] = v.z; q_s[(k + 3) * 68 + i] = v.w;
    }

    float tv[4][4];
    int   ti[4][4];
    #pragma unroll
    for (int r = 0; r < 4; r++)
        #pragma unroll
        for (int s = 0; s < 4; s++) { tv[r][s] = -2.0f; ti[r][s] = 0x7FFFFFFF; }

    for (int ch = 0; ch < CKEYS / 64; ch++) {
        int cbase = c0 + ch * 64;
        __syncthreads();
        #pragma unroll
        for (int p = 0; p < 4; p++) {
            int flat = p * 1024 + tid * 4;
            int i = flat >> 6, k = flat & 63;
            float4 v = *(const float4*)(kn + (size_t)(cbase + i) * 64 + k);
            k_s[(k + 0) * 68 + i] = v.x; k_s[(k + 1) * 68 + i] = v.y;
            k_s[(k + 2) * 68 + i] = v.z; k_s[(k + 3) * 68 + i] = v.w;
        }
        __syncthreads();

        float acc[16];
        #pragma unroll
        for (int q = 0; q < 16; q++) acc[q] = 0.f;
        #pragma unroll
        for (int k = 0; k < 64; k++) {
            float4 a = *(const float4*)(q_s + k * 68 + ty * 4);
            float4 b = *(const float4*)(k_s + k * 68 + tx * 4);
            acc[0]+=a.x*b.x; acc[1]+=a.x*b.y; acc[2]+=a.x*b.z; acc[3]+=a.x*b.w;
            acc[4]+=a.y*b.x; acc[5]+=a.y*b.y; acc[6]+=a.y*b.z; acc[7]+=a.y*b.w;
            acc[8]+=a.z*b.x; acc[9]+=a.z*b.y; acc[10]+=a.z*b.z; acc[11]+=a.z*b.w;
            acc[12]+=a.w*b.x; acc[13]+=a.w*b.y; acc[14]+=a.w*b.z; acc[15]+=a.w*b.w;
        }
        #pragma unroll
        for (int r = 0; r < 4; r++) {
            #pragma unroll
            for (int c = 0; c < 4; c++) {
                float v = acc[r * 4 + c];
                int id = cbase + tx * 4 + c;
                if (v > tv[r][3]) {
                    if (v > tv[r][0]) {
                        tv[r][3]=tv[r][2]; ti[r][3]=ti[r][2];
                        tv[r][2]=tv[r][1]; ti[r][2]=ti[r][1];
                        tv[r][1]=tv[r][0]; ti[r][1]=ti[r][0];
                        tv[r][0]=v; ti[r][0]=id;
                    } else if (v > tv[r][1]) {
                        tv[r][3]=tv[r][2]; ti[r][3]=ti[r][2];
                        tv[r][2]=tv[r][1]; ti[r][2]=ti[r][1];
                        tv[r][1]=v; ti[r][1]=id;
                    } else if (v > tv[r][2]) {
                        tv[r][3]=tv[r][2]; ti[r][3]=ti[r][2];
                        tv[r][2]=v; ti[r][2]=id;
                    } else {
                        tv[r][3]=v; ti[r][3]=id;
                    }
                }
            }
        }
    }

    __syncthreads();
    float* cv = q_s;
    int*   ci = (int*)k_s;
    #pragma unroll
    for (int r = 0; r < 4; r++) {
        int row = ty * 4 + r;
        #pragma unroll
        for (int s = 0; s < 4; s++) {
            cv[row * 64 + tx * 4 + s] = tv[r][s];
            ci[row * 64 + tx * 4 + s] = ti[r][s];
        }
    }
    __syncthreads();
    if (tid < 64) {
        float bv0=-3.f,bv1=-3.f,bv2=-3.f,bv3=-3.f;
        int bi0=0x7FFFFFFF,bi1=0x7FFFFFFF,bi2=0x7FFFFFFF,bi3=0x7FFFFFFF;
        for (int s = 0; s < 64; s++) {
            float v = cv[tid * 64 + s];
            int id = ci[tid * 64 + s];
            if (BETTER(v, id, bv3, bi3)) {
                if (BETTER(v, id, bv0, bi0))      { bv3=bv2;bi3=bi2; bv2=bv1;bi2=bi1; bv1=bv0;bi1=bi0; bv0=v;bi0=id; }
                else if (BETTER(v, id, bv1, bi1)) { bv3=bv2;bi3=bi2; bv2=bv1;bi2=bi1; bv1=v;bi1=id; }
                else if (BETTER(v, id, bv2, bi2)) { bv3=bv2;bi3=bi2; bv2=v;bi2=id; }
                else                              { bv3=v;bi3=id; }
            }
        }
        int base = ((row0 + tid) * CSPLIT + blockIdx.y) * 4;
        pval[base + 0] = bv0; pval[base + 1] = bv1; pval[base + 2] = bv2; pval[base + 3] = bv3;
        pidx[base + 0] = bi0; pidx[base + 1] = bi1; pidx[base + 2] = bi2; pidx[base + 3] = bi3;
    }
}

__global__ void ep_kernel(const float* __restrict__ pval, const int* __restrict__ pidx,
                          const float* __restrict__ cvals, const float* __restrict__ vmem,
                          float* __restrict__ vc)
{
    int b = blockIdx.x;
    __shared__ int sidx[4];
    if (threadIdx.x == 0) {
        float bv0=-3.f,bv1=-3.f,bv2=-3.f,bv3=-3.f;
        int bi0=0x7FFFFFFF,bi1=0x7FFFFFFF,bi2=0x7FFFFFFF,bi3=0x7FFFFFFF;
        for (int j = 0; j < CSPLIT * 4; j++) {
            float v = pval[b * (CSPLIT * 4) + j];
            int id = pidx[b * (CSPLIT * 4) + j];
            if (BETTER(v, id, bv3, bi3)) {
                if (BETTER(v, id, bv0, bi0))      { bv3=bv2;bi3=bi2; bv2=bv1;bi2=bi1; bv1=bv0;bi1=bi0; bv0=v;bi0=id; }
                else if (BETTER(v, id, bv1, bi1)) { bv3=bv2;bi3=bi2; bv2=bv1;bi2=bi1; bv1=v;bi1=id; }
                else if (BETTER(v, id, bv2, bi2)) { bv3=bv2;bi3=bi2; bv2=v;bi2=id; }
                else                              { bv3=v;bi3=id; }
            }
        }
        sidx[0]=bi0; sidx[1]=bi1; sidx[2]=bi2; sidx[3]=bi3;
    }
    __syncthreads();
    int e = threadIdx.x;
    float s = cvals[(size_t)sidx[0] * 64 + e];
    s += cvals[(size_t)sidx[1] * 64 + e];
    s += cvals[(size_t)sidx[2] * 64 + e];
    s += cvals[(size_t)sidx[3] * 64 + e];
    vc[b * 64 + e] = 0.5f * (vmem[b * 64 + e] + s * 0.25f);
}

__global__ void cf_partial_kernel(const float* __restrict__ z1, const float* __restrict__ z2,
                                  const float* __restrict__ z, const float* __restrict__ vc,
                                  float* __restrict__ part)
{
    __shared__ float red[256];
    float s = 0.f;
    for (int i = blockIdx.x * 256 + threadIdx.x; i < BB * DD; i += 256 * 256) {
        float d = 0.5f * (z1[i] + z2[i]) - z[i] - vc[i];
        s += d * d;
    }
    red[threadIdx.x] = s;
    __syncthreads();
    for (int st = 128; st > 0; st >>= 1) {
        if (threadIdx.x < st) red[threadIdx.x] += red[threadIdx.x + st];
        __syncthreads();
    }
    if (threadIdx.x == 0) part[blockIdx.x] = red[0];
}

__global__ void cf_final_kernel(const float* __restrict__ part, float* __restrict__ out)
{
    __shared__ float red[256];
    red[threadIdx.x] = part[threadIdx.x];
    __syncthreads();
    for (int st = 128; st > 0; st >>= 1) {
        if (threadIdx.x < st) red[threadIdx.x] += red[threadIdx.x + st];
        __syncthreads();
    }
    if (threadIdx.x == 0) out[BB * DD] = red[0] * (1.0f / (float)(BB * DD));
}

extern "C" void kernel_launch(void* const* d_in, const int* in_sizes, int n_in,
                              void* d_out, int out_size)
{
    const float* z    = (const float*)d_in[0];
    const float* hot  = (const float*)d_in[2];
    const float* gap  = (const float*)d_in[3];
    const float* Wq   = (const float*)d_in[4];
    const float* bq   = (const float*)d_in[5];
    const float* Wf   = (const float*)d_in[6];
    const float* bf   = (const float*)d_in[7];
    const float* mem  = (const float*)d_in[8];
    const float* Wk   = (const float*)d_in[9];
    const float* Wo   = (const float*)d_in[10];
    const float* ck   = (const float*)d_in[11];
    const float* cvals= (const float*)d_in[12];
    const float* aemb = (const float*)d_in[13];
    const float* Wih  = (const float*)d_in[14];
    const float* Whh  = (const float*)d_in[15];
    const float* bih  = (const float*)d_in[16];
    const float* bhh  = (const float*)d_in[17];
    const float* h0   = (const float*)d_in[18];
    const float* Wo1  = (const float*)d_in[19];
    const float* bo1  = (const float*)d_in[20];
    const float* Wo2  = (const float*)d_in[21];
    const float* bo2  = (const float*)d_in[22];
    const int*   acts = (const int*)d_in[23];
    float* out = (float*)d_out;

    float* scr = nullptr;
    cudaGetSymbolAddress((void**)&scr, d_scr);

    // tensor-product memory folded to 64x64 A
    prepA_kernel<<<8, 256>>>(mem, Wk, Wo, scr + OFF_APART);
    reduceAT_kernel<<<16, 256>>>(scr + OFF_APART, scr + OFF_AT);

    // query, qn, kn, v_mem
    mul_kernel<<<1024, 256>>>(z, hot, scr + OFF_ZH);
    gemm_kernel<<<dim3(64, 1), 256>>>(scr + OFF_ZH, Wq, bq, scr + OFF_Q, 64, 64, 0);
    normalize_rows_kernel<<<512, 256>>>(scr + OFF_Q, scr + OFF_QN);
    normalize_rows_kernel<<<2048, 256>>>(ck, scr + OFF_KN);
    gemm_kernel<<<dim3(64, 1), 256>>>(scr + OFF_Q, scr + OFF_AT, scr + OFF_ZERO,
                                      scr + OFF_VMEM, 64, 64, 0);

    // episodic recall
    sims_topk_kernel<<<dim3(64, CSPLIT), 256>>>(scr + OFF_QN, scr + OFF_KN,
                                                scr + OFF_PVAL, (int*)(scr + OFF_PIDX));
    ep_kernel<<<BB, 64>>>(scr + OFF_PVAL, (int*)(scr + OFF_PIDX), cvals,
                          scr + OFF_VMEM, scr + OFF_VC);

    // GRU rollout, T=2
    hinit_kernel<<<2048, 256>>>(h0, scr + OFF_H0B);
    // t = 0
    buildx_kernel<<<2048, 256>>>(z, aemb, acts, 0, scr + OFF_X);
    gemm_kernel<<<dim3(64, 6), 256>>>(scr + OFF_X,   Wih, bih, scr + OFF_GI, 384, 128, 0);
    gemm_kernel<<<dim3(64, 6), 256>>>(scr + OFF_H0B, Whh, bhh, scr + OFF_GH, 384, 128, 0);
    gates_kernel<<<2048, 256>>>(scr + OFF_GI, scr + OFF_GH, scr + OFF_H0B, scr + OFF_H2A);
    gemm_kernel<<<dim3(64, 2), 256>>>(scr + OFF_H2A, Wo1, bo1, scr + OFF_HID, 128, 128, 1);
    gemm_kernel<<<dim3(64, 1), 256>>>(scr + OFF_HID, Wo2, bo2, scr + OFF_Z1, 64, 128, 0);
    // t = 1
    buildx_kernel<<<2048, 256>>>(scr + OFF_Z1, aemb, acts, 1, scr + OFF_X);
    gemm_kernel<<<dim3(64, 6), 256>>>(scr + OFF_X,   Wih, bih, scr + OFF_GI, 384, 128, 0);
    gemm_kernel<<<dim3(64, 6), 256>>>(scr + OFF_H2A, Whh, bhh, scr + OFF_GH, 384, 128, 0);
    gates_kernel<<<2048, 256>>>(scr + OFF_GI, scr + OFF_GH, scr + OFF_H2A, scr + OFF_H2B);
    gemm_kernel<<<dim3(64, 2), 256>>>(scr + OFF_H2B, Wo1, bo1, scr + OFF_HID, 128, 128, 1);
    gemm_kernel<<<dim3(64, 1), 256>>>(scr + OFF_HID, Wo2, bo2, scr + OFF_Z2, 64, 128, 0);

    // cf loss
    cf_partial_kernel<<<256, 256>>>(scr + OFF_Z1, scr + OFF_Z2, z, scr + OFF_VC, scr + OFF_CFP);
    cf_final_kernel<<<1, 256>>>(scr + OFF_CFP, out);

    // fusion + masked update
    cat_kernel<<<2048, 256>>>(z, scr + OFF_VC, scr + OFF_CAT);
    gemm_kernel<<<dim3(64, 1), 256>>>(scr + OFF_CAT, Wf, bf, scr + OFF_ZE, 64, 128, 0);
    select_kernel<<<1024, 256>>>(z, scr + OFF_ZE, gap, out);
}